// round 17
// baseline (speedup 1.0000x reference)
#include <cuda_runtime.h>
#include <cuda_bf16.h>
#include <cstdint>
#include <cstddef>

#define N_NODES  100000
#define N_EDGES  300000
#define N_GRAPHS 2048
#define F_ATOM   40
#define D_IN     128
#define D_HID    256
#define D_OUT    512

// ---------------- scratch ----------------
__device__ float g_bufA[(size_t)N_NODES * D_OUT];
__device__ float g_bufB[(size_t)N_NODES * D_OUT];
__device__ float g_bufZ[(size_t)N_NODES * D_HID];
__device__ float g_pooled[(size_t)N_GRAPHS * D_OUT];
__device__ float g_wT[6][(size_t)512 * 512];   // pre-transposed+rounded weights
__device__ int   g_is64;

// ---------------- index dtype detection ----------------
__global__ void detect_kernel(const unsigned int* __restrict__ w, int n_words) {
    __shared__ unsigned int sh[32];
    unsigned int acc = 0;
    int nhalf = n_words >> 1;
    for (int i = threadIdx.x; i < nhalf; i += blockDim.x)
        acc |= w[2 * i + 1];
    #pragma unroll
    for (int o = 16; o > 0; o >>= 1) acc |= __shfl_down_sync(0xFFFFFFFFu, acc, o);
    if ((threadIdx.x & 31) == 0) sh[threadIdx.x >> 5] = acc;
    __syncthreads();
    if (threadIdx.x == 0) {
        unsigned int t = 0;
        for (int i = 0; i < (int)(blockDim.x >> 5); i++) t |= sh[i];
        g_is64 = (t == 0u) ? 1 : 0;
    }
}

__device__ __forceinline__ long long load_idx(const void* __restrict__ p, int i) {
    if (g_is64) return ((const long long*)p)[i];
    return (long long)(((const int*)p)[i]);
}

__device__ __forceinline__ unsigned int f2tf32(float f) {
    unsigned int u;
    asm("cvt.rna.tf32.f32 %0, %1;" : "=r"(u) : "f"(f));
    return u;
}

// ---------------- embed (+ fused z0 = (1+eps[0])*h) ----------------
__global__ void embed_kernel(const float* __restrict__ x, const float* __restrict__ W,
                             const float* __restrict__ b, float* __restrict__ out,
                             float* __restrict__ Z, const float* __restrict__ epsv) {
    __shared__ float xs[4][F_ATOM];
    int r0 = blockIdx.x * 4;
    int t  = threadIdx.x;
    for (int i = t; i < 4 * F_ATOM; i += 128) {
        int r = i / F_ATOM, c = i % F_ATOM;
        if (r0 + r < N_NODES) xs[r][c] = x[(size_t)(r0 + r) * F_ATOM + c];
    }
    __syncthreads();
    float bj = b[t];
    float ze = 1.0f + epsv[0];
    #pragma unroll
    for (int r = 0; r < 4; r++) {
        if (r0 + r >= N_NODES) return;
        float acc = bj;
        #pragma unroll
        for (int k = 0; k < F_ATOM; k++)
            acc = fmaf(xs[r][k], W[k * D_IN + t], acc);
        out[(size_t)(r0 + r) * D_IN + t] = acc;
        Z[(size_t)(r0 + r) * D_IN + t]   = ze * acc;
    }
}

// ---------------- edge scatter ----------------
__global__ void edge_agg_kernel(float* __restrict__ z, const float* __restrict__ h,
                                const void* __restrict__ ei, int D) {
    int warp = (int)((blockIdx.x * (size_t)blockDim.x + threadIdx.x) >> 5);
    int lane = threadIdx.x & 31;
    if (warp >= N_EDGES) return;
    long long s = load_idx(ei, warp);
    long long d = load_idx(ei, N_EDGES + warp);
    const float* hs = h + (size_t)s * D;
    float*       zd = z + (size_t)d * D;
    for (int c = lane; c < D; c += 32)
        atomicAdd(&zd[c], hs[c]);
}

// ---------------- weight transpose + tf32 round: Wt[n][k] = rna(W[k][n]) ----------------
__global__ void transpose_w_kernel(const float* __restrict__ W, float* __restrict__ Wt,
                                   int K, int N) {
    __shared__ float tile[32][33];
    int n0 = blockIdx.x * 32, k0 = blockIdx.y * 32;
    int tx = threadIdx.x & 31, ty = threadIdx.x >> 5;   // 256 threads = 32x8
    #pragma unroll
    for (int i = ty; i < 32; i += 8)
        tile[i][tx] = W[(size_t)(k0 + i) * N + n0 + tx];
    __syncthreads();
    #pragma unroll
    for (int i = ty; i < 32; i += 8)
        Wt[(size_t)(n0 + i) * K + k0 + tx] = __uint_as_float(f2tf32(tile[tx][i]));
}

// ---------------- tf32 tensor-core GEMM, pipelined, LDS.64 fragment layout ----------------
// C[M,N] = act(A[M,K] @ Wt[N,K]^T + bias). BM=128 BN=128 BK=16, 256 threads, warp tile 64x32.
// Wt is pre-rounded tf32 (bit-exact vs rounding at load). cvt_a: round A at load (Z path).
// round_c: store rna-rounded C (hnext path, consumed only by the next GEMM -> bit-identical).
#define BM 128
#define BN 128
#define BK 16
#define MP 132

__global__ __launch_bounds__(256, 2)
void gemm_tf32(const float* __restrict__ A, const float* __restrict__ Wt,
               const float* __restrict__ bias, float* __restrict__ C,
               int M, int N, int K, int do_relu, int cvt_a, int round_c,
               float* __restrict__ Z, const float* __restrict__ epsv, int el) {
    __shared__ unsigned int As[2][2][4][MP][2];   // [buf][kk][lq][m][half]
    __shared__ unsigned int Bs[2][2][4][MP][2];   // [buf][kk][lq][n][half]

    int tid  = threadIdx.x;
    int lane = tid & 31;
    int warp = tid >> 5;
    int wr = warp & 1;
    int wc = warp >> 1;
    int block_row = blockIdx.y * BM;
    int block_col = blockIdx.x * BN;

    int a_r  = tid >> 1;          // A loader: row 0..127
    int a_kk = tid & 1;           // k-slab 0/1
    int n_l  = tid & 127;         // B loader: col 0..127
    int b_kk = tid >> 7;          // k-slab 0/1

    float c[4][4][4];
    #pragma unroll
    for (int i = 0; i < 4; i++)
        #pragma unroll
        for (int j = 0; j < 4; j++)
            c[i][j][0] = c[i][j][1] = c[i][j][2] = c[i][j][3] = 0.f;

    int grow = block_row + a_r;
    const int lq = lane & 3;
    const int lg = lane >> 2;
    int mbase = wr * 64;
    int nbase = wc * 32;

    const float* bwp = Wt + (size_t)(block_col + n_l) * K + b_kk * 8;

    float4 av0, av1, bw0, bw1;

    // ---- prologue: load tile 0 ----
    {
        av0 = make_float4(0.f,0.f,0.f,0.f); av1 = av0;
        if (grow < M) {
            const float* ap = A + (size_t)grow * K + a_kk * 8;
            av0 = *(const float4*)ap;
            av1 = *(const float4*)(ap + 4);
        }
        bw0 = *(const float4*)bwp;
        bw1 = *(const float4*)(bwp + 4);

        if (cvt_a) {
            *(uint2*)&As[0][a_kk][0][a_r][0] = make_uint2(f2tf32(av0.x), f2tf32(av1.x));
            *(uint2*)&As[0][a_kk][1][a_r][0] = make_uint2(f2tf32(av0.y), f2tf32(av1.y));
            *(uint2*)&As[0][a_kk][2][a_r][0] = make_uint2(f2tf32(av0.z), f2tf32(av1.z));
            *(uint2*)&As[0][a_kk][3][a_r][0] = make_uint2(f2tf32(av0.w), f2tf32(av1.w));
        } else {
            *(uint2*)&As[0][a_kk][0][a_r][0] = make_uint2(__float_as_uint(av0.x), __float_as_uint(av1.x));
            *(uint2*)&As[0][a_kk][1][a_r][0] = make_uint2(__float_as_uint(av0.y), __float_as_uint(av1.y));
            *(uint2*)&As[0][a_kk][2][a_r][0] = make_uint2(__float_as_uint(av0.z), __float_as_uint(av1.z));
            *(uint2*)&As[0][a_kk][3][a_r][0] = make_uint2(__float_as_uint(av0.w), __float_as_uint(av1.w));
        }
        *(uint2*)&Bs[0][b_kk][0][n_l][0] = make_uint2(__float_as_uint(bw0.x), __float_as_uint(bw1.x));
        *(uint2*)&Bs[0][b_kk][1][n_l][0] = make_uint2(__float_as_uint(bw0.y), __float_as_uint(bw1.y));
        *(uint2*)&Bs[0][b_kk][2][n_l][0] = make_uint2(__float_as_uint(bw0.z), __float_as_uint(bw1.z));
        *(uint2*)&Bs[0][b_kk][3][n_l][0] = make_uint2(__float_as_uint(bw0.w), __float_as_uint(bw1.w));
    }
    __syncthreads();

    int buf = 0;
    for (int k0 = 0; k0 < K; k0 += BK) {
        bool has_next = (k0 + BK) < K;
        // ---- issue global loads for next tile ----
        if (has_next) {
            int kn = k0 + BK;
            av0 = make_float4(0.f,0.f,0.f,0.f); av1 = av0;
            if (grow < M) {
                const float* ap = A + (size_t)grow * K + kn + a_kk * 8;
                av0 = *(const float4*)ap;
                av1 = *(const float4*)(ap + 4);
            }
            bw0 = *(const float4*)(bwp + kn);
            bw1 = *(const float4*)(bwp + kn + 4);
        }

        // ---- compute current tile ----
        #pragma unroll
        for (int kk = 0; kk < 2; kk++) {
            unsigned int af[4][4], bf[4][2];
            #pragma unroll
            for (int mi = 0; mi < 4; mi++) {
                int mb = mbase + mi * 16 + lg;
                uint2 alo = *(const uint2*)&As[buf][kk][lq][mb][0];
                uint2 ahi = *(const uint2*)&As[buf][kk][lq][mb + 8][0];
                af[mi][0] = alo.x; af[mi][2] = alo.y;
                af[mi][1] = ahi.x; af[mi][3] = ahi.y;
            }
            #pragma unroll
            for (int ni = 0; ni < 4; ni++) {
                int nb = nbase + ni * 8 + lg;
                uint2 bu = *(const uint2*)&Bs[buf][kk][lq][nb][0];
                bf[ni][0] = bu.x; bf[ni][1] = bu.y;
            }
            #pragma unroll
            for (int mi = 0; mi < 4; mi++)
                #pragma unroll
                for (int ni = 0; ni < 4; ni++) {
                    asm volatile(
                        "mma.sync.aligned.m16n8k8.row.col.f32.tf32.tf32.f32 "
                        "{%0,%1,%2,%3}, {%4,%5,%6,%7}, {%8,%9}, {%0,%1,%2,%3};"
                        : "+f"(c[mi][ni][0]), "+f"(c[mi][ni][1]),
                          "+f"(c[mi][ni][2]), "+f"(c[mi][ni][3])
                        : "r"(af[mi][0]), "r"(af[mi][1]), "r"(af[mi][2]), "r"(af[mi][3]),
                          "r"(bf[ni][0]), "r"(bf[ni][1]));
                }
        }

        // ---- store next tile into the other buffer ----
        if (has_next) {
            int nb = buf ^ 1;
            if (cvt_a) {
                *(uint2*)&As[nb][a_kk][0][a_r][0] = make_uint2(f2tf32(av0.x), f2tf32(av1.x));
                *(uint2*)&As[nb][a_kk][1][a_r][0] = make_uint2(f2tf32(av0.y), f2tf32(av1.y));
                *(uint2*)&As[nb][a_kk][2][a_r][0] = make_uint2(f2tf32(av0.z), f2tf32(av1.z));
                *(uint2*)&As[nb][a_kk][3][a_r][0] = make_uint2(f2tf32(av0.w), f2tf32(av1.w));
            } else {
                *(uint2*)&As[nb][a_kk][0][a_r][0] = make_uint2(__float_as_uint(av0.x), __float_as_uint(av1.x));
                *(uint2*)&As[nb][a_kk][1][a_r][0] = make_uint2(__float_as_uint(av0.y), __float_as_uint(av1.y));
                *(uint2*)&As[nb][a_kk][2][a_r][0] = make_uint2(__float_as_uint(av0.z), __float_as_uint(av1.z));
                *(uint2*)&As[nb][a_kk][3][a_r][0] = make_uint2(__float_as_uint(av0.w), __float_as_uint(av1.w));
            }
            *(uint2*)&Bs[nb][b_kk][0][n_l][0] = make_uint2(__float_as_uint(bw0.x), __float_as_uint(bw1.x));
            *(uint2*)&Bs[nb][b_kk][1][n_l][0] = make_uint2(__float_as_uint(bw0.y), __float_as_uint(bw1.y));
            *(uint2*)&Bs[nb][b_kk][2][n_l][0] = make_uint2(__float_as_uint(bw0.z), __float_as_uint(bw1.z));
            *(uint2*)&Bs[nb][b_kk][3][n_l][0] = make_uint2(__float_as_uint(bw0.w), __float_as_uint(bw1.w));
        }
        __syncthreads();
        buf ^= 1;
    }

    // epilogue: bias + optional relu (+ optional round-to-tf32, + optional fused Z)
    float ze = (Z != nullptr) ? (1.0f + epsv[el]) : 0.0f;
    #pragma unroll
    for (int mi = 0; mi < 4; mi++) {
        int r0 = block_row + mbase + mi * 16 + lg;
        int r1 = r0 + 8;
        #pragma unroll
        for (int ni = 0; ni < 4; ni++) {
            int gc = block_col + nbase + ni * 8 + lq * 2;
            float2 bvv = *(const float2*)(bias + gc);
            float2 v0, v1;
            v0.x = c[mi][ni][0] + bvv.x;  v0.y = c[mi][ni][1] + bvv.y;
            v1.x = c[mi][ni][2] + bvv.x;  v1.y = c[mi][ni][3] + bvv.y;
            if (do_relu) {
                v0.x = fmaxf(v0.x, 0.f); v0.y = fmaxf(v0.y, 0.f);
                v1.x = fmaxf(v1.x, 0.f); v1.y = fmaxf(v1.y, 0.f);
            }
            if (round_c) {
                v0.x = __uint_as_float(f2tf32(v0.x)); v0.y = __uint_as_float(f2tf32(v0.y));
                v1.x = __uint_as_float(f2tf32(v1.x)); v1.y = __uint_as_float(f2tf32(v1.y));
            }
            if (r0 < M) {
                *(float2*)(C + (size_t)r0 * N + gc) = v0;
                if (Z) *(float2*)(Z + (size_t)r0 * N + gc) = make_float2(ze * v0.x, ze * v0.y);
            }
            if (r1 < M) {
                *(float2*)(C + (size_t)r1 * N + gc) = v1;
                if (Z) *(float2*)(Z + (size_t)r1 * N + gc) = make_float2(ze * v1.x, ze * v1.y);
            }
        }
    }
}

// ---------------- zero pooled ----------------
__global__ void zero_kernel(float* __restrict__ p, size_t n) {
    size_t i = (size_t)blockIdx.x * blockDim.x + threadIdx.x;
    size_t stride = (size_t)gridDim.x * blockDim.x;
    for (; i < n; i += stride) p[i] = 0.0f;
}

// ---------------- pool: batch SORTED -> run-compress ----------------
__global__ void pool_kernel(const float* __restrict__ h, const void* __restrict__ batch,
                            float* __restrict__ pooled) {
    int n0 = blockIdx.x * 64;
    if (n0 >= N_NODES) return;
    int t = threadIdx.x;
    int nEnd = min(n0 + 64, N_NODES);
    float acc[4] = {0.f, 0.f, 0.f, 0.f};
    long long curg = load_idx(batch, n0);
    for (int n = n0; n < nEnd; n++) {
        long long g = load_idx(batch, n);
        if (g != curg) {
            #pragma unroll
            for (int i = 0; i < 4; i++) {
                atomicAdd(&pooled[(size_t)curg * D_OUT + t + 128 * i], acc[i]);
                acc[i] = 0.f;
            }
            curg = g;
        }
        #pragma unroll
        for (int i = 0; i < 4; i++)
            acc[i] += h[(size_t)n * D_OUT + t + 128 * i];
    }
    #pragma unroll
    for (int i = 0; i < 4; i++)
        atomicAdd(&pooled[(size_t)curg * D_OUT + t + 128 * i], acc[i]);
}

// ---------------- head ----------------
__global__ void task_kernel(const float* __restrict__ pooled, const float* __restrict__ Wt,
                            const float* __restrict__ bt, float* __restrict__ out) {
    int g = blockIdx.x;
    int t = threadIdx.x;
    float s = 0.f;
    #pragma unroll
    for (int i = 0; i < 4; i++)
        s += pooled[(size_t)g * D_OUT + t + 128 * i] * Wt[t + 128 * i];
    #pragma unroll
    for (int o = 16; o > 0; o >>= 1) s += __shfl_down_sync(0xFFFFFFFFu, s, o);
    __shared__ float red[4];
    if ((t & 31) == 0) red[t >> 5] = s;
    __syncthreads();
    if (t == 0) out[g] = red[0] + red[1] + red[2] + red[3] + bt[0];
}

// ---------------- launch ----------------
extern "C" void kernel_launch(void* const* d_in, const int* in_sizes, int n_in,
                              void* d_out, int out_size) {
    const float* x       = (const float*)d_in[0];
    const void*  ei      = d_in[1];
    const void*  batch   = d_in[2];
    const float* W_embed = (const float*)d_in[3];
    const float* b_embed = (const float*)d_in[4];
    const float* eps     = (const float*)d_in[5];
    const float* W1[3]   = {(const float*)d_in[6],  (const float*)d_in[10], (const float*)d_in[14]};
    const float* b1[3]   = {(const float*)d_in[7],  (const float*)d_in[11], (const float*)d_in[15]};
    const float* W2[3]   = {(const float*)d_in[8],  (const float*)d_in[12], (const float*)d_in[16]};
    const float* b2[3]   = {(const float*)d_in[9],  (const float*)d_in[13], (const float*)d_in[17]};
    const float* W_task  = (const float*)d_in[18];
    const float* b_task  = (const float*)d_in[19];
    float* out = (float*)d_out;

    float *bufA, *bufB, *bufZ, *pooled, *wT0;
    cudaGetSymbolAddress((void**)&bufA, g_bufA);
    cudaGetSymbolAddress((void**)&bufB, g_bufB);
    cudaGetSymbolAddress((void**)&bufZ, g_bufZ);
    cudaGetSymbolAddress((void**)&pooled, g_pooled);
    cudaGetSymbolAddress((void**)&wT0, g_wT);

    const int Din[3] = {D_IN,  D_HID, D_HID};
    const int Dh[3]  = {D_HID, D_HID, D_OUT};
    float* wT[6];
    for (int i = 0; i < 6; i++) wT[i] = wT0 + (size_t)i * 512 * 512;

    detect_kernel<<<1, 1024>>>((const unsigned int*)ei, in_sizes[1]);

    // upfront: transpose + tf32-round all 6 MLP weights (Wt[n][k] = rna(W[k][n]))
    for (int l = 0; l < 3; l++) {
        int dk = Din[l], dh = Dh[l];
        transpose_w_kernel<<<dim3(dh / 32, dk / 32), 256>>>(W1[l], wT[2 * l],     dk, dh);
        transpose_w_kernel<<<dim3(dh / 32, dh / 32), 256>>>(W2[l], wT[2 * l + 1], dh, dh);
    }

    embed_kernel<<<N_NODES / 4, 128>>>(x, W_embed, b_embed, bufA, bufZ, eps);

    float* hcur = bufA;
    float* hnext = bufB;
    for (int l = 0; l < 3; l++) {
        int dk = Din[l], dh = Dh[l];
        // bufZ holds (1+eps[l])*hcur (from embed or previous fused epilogue)
        edge_agg_kernel<<<(N_EDGES * 32 + 255) / 256, 256>>>(bufZ, hcur, ei, dk);
        // GEMM1: hnext = rna(relu(Z @ W1 + b1))   (A needs cvt; C rounded for GEMM2)
        {
            dim3 grid(dh / BN, (N_NODES + BM - 1) / BM);
            gemm_tf32<<<grid, 256>>>(bufZ, wT[2 * l], b1[l], hnext, N_NODES, dh, dk,
                                     1, /*cvt_a=*/1, /*round_c=*/1, nullptr, eps, 0);
        }
        // GEMM2: hcur = act(hnext @ W2 + b2)   (A already tf32; fused Z for next layer)
        {
            dim3 grid(dh / BN, (N_NODES + BM - 1) / BM);
            gemm_tf32<<<grid, 256>>>(hnext, wT[2 * l + 1], b2[l], hcur, N_NODES, dh, dh,
                                     (l < 2) ? 1 : 0, /*cvt_a=*/0, /*round_c=*/0,
                                     (l < 2) ? bufZ : nullptr, eps, l + 1);
        }
    }

    zero_kernel<<<256, 256>>>(pooled, (size_t)N_GRAPHS * D_OUT);
    pool_kernel<<<(N_NODES + 63) / 64, 128>>>(hcur, batch, pooled);

    task_kernel<<<N_GRAPHS, 128>>>(pooled, W_task, b_task, out);
}